// round 8
// baseline (speedup 1.0000x reference)
#include <cuda_runtime.h>
#include <cuda_bf16.h>
#include <math.h>
#include <float.h>

#define BATCH 4
#define SEQ   512
#define CDIM  768
#define NHEAD 12
#define HS    64
#define BH    (BATCH*NHEAD)      // 48
#define DW    8                  // warps (tokens) per dpp block

// ---------------- device scratch (allocation forbidden) ----------------
__device__ float g_q  [BH*SEQ*HS];          // fp32 q (feeds sim)
__device__ float g_k  [BH*SEQ*HS];          // fp32 k (feeds sim + DPP gram)
__device__ float g_v  [BH*SEQ*HS];          // fp32 v
__device__ float g_sim[(size_t)BH*SEQ*SEQ]; // q_i . k_j
__device__ float g_y  [BATCH*SEQ*CDIM];     // attention output

// tf32 split operands (stored as fp32 bit patterns)
__device__ float g_xh [BATCH*SEQ*CDIM],  g_xl [BATCH*SEQ*CDIM];
__device__ float g_Wah[CDIM*3*CDIM],     g_Wal[CDIM*3*CDIM];
__device__ float g_Wph[CDIM*CDIM],       g_Wpl[CDIM*CDIM];
__device__ float g_yh [BATCH*SEQ*CDIM],  g_yl [BATCH*SEQ*CDIM];

// ---------------- helpers ----------------
__device__ __forceinline__ float tf32_rnd(float x)
{
    unsigned r;
    asm("cvt.rna.tf32.f32 %0, %1;" : "=r"(r) : "f"(x));
    return __uint_as_float(r);
}

__device__ __forceinline__ void mma_tf32(float* c, const float* a, float b0, float b1)
{
    asm volatile("mma.sync.aligned.m16n8k8.row.col.f32.tf32.tf32.f32 "
        "{%0,%1,%2,%3}, {%4,%5,%6,%7}, {%8,%9}, {%0,%1,%2,%3};"
        : "+f"(c[0]), "+f"(c[1]), "+f"(c[2]), "+f"(c[3])
        : "r"(__float_as_uint(a[0])), "r"(__float_as_uint(a[1])),
          "r"(__float_as_uint(a[2])), "r"(__float_as_uint(a[3])),
          "r"(__float_as_uint(b0)),   "r"(__float_as_uint(b1)));
}

__device__ __forceinline__ void cp16(unsigned dst, const float* src)
{
    asm volatile("cp.async.ca.shared.global [%0], [%1], 16;" :: "r"(dst), "l"(src));
}

// ---------------- split kernel: fp32 -> (hi,lo) tf32 pair ----------------
__global__ __launch_bounds__(256)
void split_kernel(const float* __restrict__ src, int which, int n)
{
    int i = (blockIdx.x*256 + threadIdx.x) * 4;
    if (i >= n) return;
    const float* s = src ? src : g_y;
    float *hi, *lo;
    switch (which) {
        case 0: hi = g_xh;  lo = g_xl;  break;
        case 1: hi = g_Wah; lo = g_Wal; break;
        case 2: hi = g_Wph; lo = g_Wpl; break;
        default: hi = g_yh; lo = g_yl;  break;
    }
    float4 v = *(const float4*)(s + i);
    float4 h, l;
    h.x = tf32_rnd(v.x); l.x = tf32_rnd(v.x - h.x);
    h.y = tf32_rnd(v.y); l.y = tf32_rnd(v.y - h.y);
    h.z = tf32_rnd(v.z); l.z = tf32_rnd(v.z - h.z);
    h.w = tf32_rnd(v.w); l.w = tf32_rnd(v.w - h.w);
    *(float4*)&hi[i] = h;
    *(float4*)&lo[i] = l;
}

// ---------------- qkv scatter ----------------
__device__ __forceinline__ void scatter_qkv(int row, int gc, float v0, float v1)
{
    int sect = gc / CDIM;              // 0=q 1=k 2=v
    int cc = gc - sect*CDIM;
    int h = cc >> 6, dd = cc & 63;
    int bb = row >> 9, t = row & 511;
    size_t off = ((size_t)(bb*NHEAD + h)*SEQ + t)*HS + dd;
    float* dst = (sect == 0) ? g_q : (sect == 1 ? g_k : g_v);
    *(float2*)&dst[off] = make_float2(v0, v1);
}

// ---------------- 3xTF32 GEMM, cp.async 3-stage pipeline, 1 sync/chunk ----
// CTA 128x128, K-chunk 8. Stage layout (floats):
//   A: [split][m(128)][pitch 12, k 0..7]        at 0      (3072 floats)
//   B: [split][k(8)][pitch 136, n 0..127]       at 3072   (2176 floats)
#define STG 5248
#define NSTAGE 3
#define GEMM_SMEM (NSTAGE*STG*4)

__global__ __launch_bounds__(256, 2)
void tf32_gemm(const float* __restrict__ bias, float* __restrict__ Cout,
               int M, int N, int K, int mode)
{
    extern __shared__ __align__(16) float sm[];

    const float *Ah, *Al, *Bh, *Bl;
    if (mode == 0) { Ah = g_xh; Al = g_xl; Bh = g_Wah; Bl = g_Wal; }
    else           { Ah = g_yh; Al = g_yl; Bh = g_Wph; Bl = g_Wpl; }

    const int tid = threadIdx.x, lane = tid & 31, wid = tid >> 5;
    const int bm = blockIdx.y, bn = blockIdx.x;
    const int wm = wid & 3, wn = wid >> 2;
    const int g = lane >> 2, t = lane & 3;

    const unsigned smbase = (unsigned)__cvta_generic_to_shared(sm);

    // per-thread copy coords (ids tid and tid+256)
    int aSp[2], aM[2], aKq[2], bSp[2], bK[2], bN4[2];
#pragma unroll
    for (int h = 0; h < 2; h++) {
        int id = tid + h*256;
        aSp[h] = id >> 8; int ra = id & 255; aM[h] = ra >> 1; aKq[h] = (ra & 1) * 4;
        bSp[h] = id >> 8; int rb = id & 255; bK[h] = rb >> 5; bN4[h] = (rb & 31) * 4;
    }

    float acc[2][8][4];
#pragma unroll
    for (int a = 0; a < 2; a++)
#pragma unroll
        for (int b = 0; b < 8; b++)
#pragma unroll
            for (int c = 0; c < 4; c++) acc[a][b][c] = 0.f;

    const int NC = K >> 3;

    auto issue = [&](int chunk) {
        unsigned base = smbase + (unsigned)((chunk % NSTAGE)*STG)*4u;
        int k0 = chunk*8;
#pragma unroll
        for (int h = 0; h < 2; h++) {
            const float* srcA = (aSp[h] ? Al : Ah) + (size_t)(bm*128 + aM[h])*K + k0 + aKq[h];
            cp16(base + (unsigned)(aSp[h]*1536 + aM[h]*12 + aKq[h])*4u, srcA);
        }
#pragma unroll
        for (int h = 0; h < 2; h++) {
            const float* srcB = (bSp[h] ? Bl : Bh) + (size_t)(k0 + bK[h])*N + bn*128 + bN4[h];
            cp16(base + (unsigned)(3072 + bSp[h]*1088 + bK[h]*136 + bN4[h])*4u, srcB);
        }
        asm volatile("cp.async.commit_group;");
    };

    // prologue: 2 chunks in flight
    issue(0);
    if (NC > 1) issue(1);

    for (int c = 0; c < NC; c++) {
        if (c + 1 < NC) {
            asm volatile("cp.async.wait_group 1;");
        } else {
            asm volatile("cp.async.wait_group 0;");
        }
        __syncthreads();
        // stage (c-1)%3's reads finished at iter c-1 (guaranteed by this sync),
        // so chunk c+2 can be issued into that buffer now and land while we
        // compute chunks c and c+1.
        if (c + 2 < NC) issue(c + 2);

        const float* S = sm + (c % NSTAGE)*STG;

        float ah[2][4], al[2][4];
#pragma unroll
        for (int mt = 0; mt < 2; mt++) {
            int m0 = (wm*32 + mt*16 + g)*12 + t;
            ah[mt][0] = S[m0];          ah[mt][1] = S[m0 + 96];      // +8 rows
            ah[mt][2] = S[m0 + 4];      ah[mt][3] = S[m0 + 100];
            al[mt][0] = S[1536 + m0];   al[mt][1] = S[1536 + m0 + 96];
            al[mt][2] = S[1536 + m0+4]; al[mt][3] = S[1536 + m0 + 100];
        }
#pragma unroll
        for (int nt = 0; nt < 8; nt++) {
            int nb = wn*64 + nt*8 + g;
            float bh0 = S[3072 + t*136 + nb];
            float bh1 = S[3072 + (t+4)*136 + nb];
            float bl0 = S[4160 + t*136 + nb];
            float bl1 = S[4160 + (t+4)*136 + nb];
#pragma unroll
            for (int mt = 0; mt < 2; mt++) {
                mma_tf32(acc[mt][nt], ah[mt], bh0, bh1);
                mma_tf32(acc[mt][nt], ah[mt], bl0, bl1);
                mma_tf32(acc[mt][nt], al[mt], bh0, bh1);
            }
        }
    }

    // epilogue
#pragma unroll
    for (int mt = 0; mt < 2; mt++) {
        int r0 = bm*128 + wm*32 + mt*16 + g;
#pragma unroll
        for (int nt = 0; nt < 8; nt++) {
            int gc = bn*128 + wn*64 + nt*8 + t*2;
            float b0 = bias[gc], b1 = bias[gc+1];
            float v00 = acc[mt][nt][0] + b0, v01 = acc[mt][nt][1] + b1;
            float v10 = acc[mt][nt][2] + b0, v11 = acc[mt][nt][3] + b1;
            if (mode == 1) {
                *(float2*)&Cout[(size_t)r0*N + gc]     = make_float2(v00, v01);
                *(float2*)&Cout[(size_t)(r0+8)*N + gc] = make_float2(v10, v11);
            } else {
                scatter_qkv(r0,     gc, v00, v01);
                scatter_qkv(r0 + 8, gc, v10, v11);
            }
        }
    }
}

// ---------------- sim: S = Q K^T per head, 3xTF32 ----------------
#define APITCH 20
__global__ __launch_bounds__(256)
void sim_tf32()
{
    const int bm = blockIdx.y, bn = blockIdx.x;
    if (bn > bm) return;                        // causal blocks only
    const int bh = blockIdx.z;

    __shared__ __align__(16) float Qs[2][128*APITCH];
    __shared__ __align__(16) float Ks[2][128*APITCH];

    const float* __restrict__ qb = g_q + (size_t)bh*SEQ*HS;
    const float* __restrict__ kb = g_k + (size_t)bh*SEQ*HS;

    const int tid = threadIdx.x, lane = tid & 31, wid = tid >> 5;
    const int wm = wid & 3, wn = wid >> 2;
    const int g = lane >> 2, t = lane & 3;

    float acc[2][8][4];
#pragma unroll
    for (int a = 0; a < 2; a++)
#pragma unroll
        for (int b = 0; b < 8; b++)
#pragma unroll
            for (int c = 0; c < 4; c++) acc[a][b][c] = 0.f;

    for (int d0 = 0; d0 < HS; d0 += 16) {
        if (d0 > 0) __syncthreads();
#pragma unroll
        for (int j = 0; j < 2; j++) {
            int id = tid*2 + j;
            int r = id >> 2, c = (id & 3)*4;
            float4 qv = *(const float4*)&qb[(size_t)(bm*128 + r)*HS + d0 + c];
            float4 kv = *(const float4*)&kb[(size_t)(bn*128 + r)*HS + d0 + c];
            float4 qh, ql, kh, kl;
            qh.x = tf32_rnd(qv.x); ql.x = tf32_rnd(qv.x - qh.x);
            qh.y = tf32_rnd(qv.y); ql.y = tf32_rnd(qv.y - qh.y);
            qh.z = tf32_rnd(qv.z); ql.z = tf32_rnd(qv.z - qh.z);
            qh.w = tf32_rnd(qv.w); ql.w = tf32_rnd(qv.w - qh.w);
            kh.x = tf32_rnd(kv.x); kl.x = tf32_rnd(kv.x - kh.x);
            kh.y = tf32_rnd(kv.y); kl.y = tf32_rnd(kv.y - kh.y);
            kh.z = tf32_rnd(kv.z); kl.z = tf32_rnd(kv.z - kh.z);
            kh.w = tf32_rnd(kv.w); kl.w = tf32_rnd(kv.w - kh.w);
            *(float4*)&Qs[0][r*APITCH + c] = qh;
            *(float4*)&Qs[1][r*APITCH + c] = ql;
            *(float4*)&Ks[0][r*APITCH + c] = kh;
            *(float4*)&Ks[1][r*APITCH + c] = kl;
        }
        __syncthreads();

#pragma unroll
        for (int ks = 0; ks < 16; ks += 8) {
            float ah[2][4], al[2][4];
#pragma unroll
            for (int mt = 0; mt < 2; mt++) {
                int m0 = (wm*32 + mt*16 + g)*APITCH + ks + t;
                int m1 = m0 + 8*APITCH;
                ah[mt][0] = Qs[0][m0];   ah[mt][1] = Qs[0][m1];
                ah[mt][2] = Qs[0][m0+4]; ah[mt][3] = Qs[0][m1+4];
                al[mt][0] = Qs[1][m0];   al[mt][1] = Qs[1][m1];
                al[mt][2] = Qs[1][m0+4]; al[mt][3] = Qs[1][m1+4];
            }
#pragma unroll
            for (int nt = 0; nt < 8; nt++) {
                int n0 = (wn*64 + nt*8 + g)*APITCH + ks + t;
                float bh0 = Ks[0][n0];
                float bh1 = Ks[0][n0+4];
                float bl0 = Ks[1][n0];
                float bl1 = Ks[1][n0+4];
#pragma unroll
                for (int mt = 0; mt < 2; mt++) {
                    mma_tf32(acc[mt][nt], ah[mt], bh0, bh1);
                    mma_tf32(acc[mt][nt], ah[mt], bl0, bl1);
                    mma_tf32(acc[mt][nt], al[mt], bh0, bh1);
                }
            }
        }
    }

    float* S = g_sim + (size_t)bh*SEQ*SEQ;
#pragma unroll
    for (int mt = 0; mt < 2; mt++) {
        int r0 = bm*128 + wm*32 + mt*16 + g;
#pragma unroll
        for (int nt = 0; nt < 8; nt++) {
            int gc = bn*128 + wn*64 + nt*8 + t*2;
            *(float2*)&S[(size_t)r0*SEQ + gc]     = make_float2(acc[mt][nt][0], acc[mt][nt][1]);
            *(float2*)&S[(size_t)(r0+8)*SEQ + gc] = make_float2(acc[mt][nt][2], acc[mt][nt][3]);
        }
    }
}

// ---------------- DPP greedy selection (unchanged, proven) ----------------
__global__ __launch_bounds__(32*DW)
void dpp_kernel()
{
    __shared__ __align__(16) float krows[DW][17][68];
    __shared__ float Gm[DW][17][17];

    const unsigned FULL = 0xffffffffu;
    const int lane = threadIdx.x & 31;
    const int wrp  = threadIdx.x >> 5;
    const int i  = blockIdx.x * DW + wrp;
    const int bh = blockIdx.y;
    const int nvalid = i + 1;

    const float* __restrict__ kb = g_k + (size_t)bh*SEQ*HS;
    const float* __restrict__ vb = g_v + (size_t)bh*SEQ*HS;
    const float* __restrict__ simRow = g_sim + ((size_t)bh*SEQ + i)*SEQ;

    float val[16];
#pragma unroll
    for (int c = 0; c < 16; c++) {
        int idx = c*32 + lane;
        val[c] = (idx < nvalid) ? simRow[idx] : -INFINITY;
    }

    float myVal = -INFINITY; int myIdx = i;
    for (int t = 0; t < 16; t++) {
        float bv = val[0]; int bc = 0;
#pragma unroll
        for (int c = 1; c < 16; c++) if (val[c] > bv) { bv = val[c]; bc = c; }
        int bg = bc*32 + lane;
#pragma unroll
        for (int off = 16; off; off >>= 1) {
            float ov = __shfl_down_sync(FULL, bv, off);
            int   og = __shfl_down_sync(FULL, bg, off);
            if (ov > bv || (ov == bv && og < bg)) { bv = ov; bg = og; }
        }
        bv = __shfl_sync(FULL, bv, 0);
        bg = __shfl_sync(FULL, bg, 0);
        if (lane == (bg & 31)) {
            int cc = bg >> 5;
#pragma unroll
            for (int c = 0; c < 16; c++) if (c == cc) val[c] = -INFINITY;
        }
        if (lane == t) { myVal = bv; myIdx = bg; }
    }
    bool availb = (lane < 16) && (myVal > -INFINITY) && (myIdx != i);
    unsigned avail = __ballot_sync(FULL, availb) & 0xFFFFu;
    int safeIdx = (lane < 16 && myVal > -INFINITY) ? myIdx : i;

    const int half = lane >> 4;
    const int hl   = lane & 15;
    for (int r = 0; r < 17; r += 2) {
        int src = r + half;
        int sl  = src & 15;
        int gv  = __shfl_sync(FULL, safeIdx, sl);
        int gidx = (src >= 16) ? i : gv;
        if (src <= 16) {
            float4 kv = ((const float4*)(kb + (size_t)gidx*HS))[hl];
            *(float4*)&krows[wrp][src][hl*4] = kv;
        }
    }
    __syncwarp();

#pragma unroll
    for (int t = 0; t < 10; t++) {
        int e = lane + 32*t;
        if (e < 289) {
            int a = e / 17, b = e - a*17;
            if (a <= b) {
                const float* ra = krows[wrp][a];
                const float* rb = krows[wrp][b];
                float acc = 0.f;
#pragma unroll
                for (int c = 0; c < 16; c++) {
                    float4 x = ((const float4*)ra)[c];
                    float4 y = ((const float4*)rb)[c];
                    acc = fmaf(x.x, y.x, acc);
                    acc = fmaf(x.y, y.y, acc);
                    acc = fmaf(x.z, y.z, acc);
                    acc = fmaf(x.w, y.w, acc);
                }
                Gm[wrp][a][b] = acc;
                Gm[wrp][b][a] = acc;
            }
        }
    }
    __syncwarp();

    const int cl = lane & 15;
    float Gii  = Gm[wrp][16][16];
    float detS = Gii;
    float curS = -logf(Gii + 1e-6f);
    int count = 1;
    float w[8];
    float w0 = Gm[wrp][cl][16] / sqrtf(Gii);
    w[0] = w0;
#pragma unroll
    for (int j = 1; j < 8; j++) w[j] = 0.f;
    float ec = Gm[wrp][cl][cl] - w0*w0;
    int selTok[8];
#pragma unroll
    for (int j = 0; j < 8; j++) selTok[j] = i;

    for (int step = 0; step < 7; step++) {
        bool av = (lane < 16) && ((avail >> lane) & 1u);
        float s = av ? (-logf(detS*ec + 1e-6f) / (float)(count + 1)) : -INFINITY;
        float bs = s; int bl = lane;
#pragma unroll
        for (int off = 16; off; off >>= 1) {
            float ov = __shfl_down_sync(FULL, bs, off);
            int   ol = __shfl_down_sync(FULL, bl, off);
            bool nb = isnan(bs), no = isnan(ov);
            bool better = (!nb && (no || ov > bs)) ||
                          (((nb && no) || (ov == bs)) && ol < bl);
            if (better) { bs = ov; bl = ol; }
        }
        bs = __shfl_sync(FULL, bs, 0);
        bl = __shfl_sync(FULL, bl, 0);
        bool anyAvail = (avail != 0u);
        bool accept = anyAvail && ((bs > curS) || (count < 2));
        if (!accept) break;

        float eb = __shfl_sync(FULL, ec, bl);
        float Lb = sqrtf(eb);
        float dot = 0.f;
#pragma unroll
        for (int j = 0; j < 7; j++) {
            float wbj = __shfl_sync(FULL, w[j], bl);
            if (j < count) dot += w[j]*wbj;
        }
        float wn = (Gm[wrp][cl][bl] - dot) / Lb;
#pragma unroll
        for (int j = 1; j < 8; j++) if (j == count) w[j] = wn;
        ec -= wn*wn;
        detS *= eb;
        curS = bs;
        int btok = __shfl_sync(FULL, myIdx, bl);
#pragma unroll
        for (int j = 1; j < 8; j++) if (j == count) selTok[j] = btok;
        count++;
        avail &= ~(1u << bl);
    }

    float a0 = 0.f, a1 = 0.f;
#pragma unroll
    for (int r = 0; r < 8; r++) {
        if (r < count) {
            const float* vr = vb + (size_t)selTok[r]*HS;
            a0 += vr[lane];
            a1 += vr[lane + 32];
        }
    }
    float cnt = (float)count;
    int bb = bh / NHEAD, h = bh % NHEAD;
    float* yo = g_y + ((size_t)(bb*SEQ + i))*CDIM + h*HS;
    yo[lane]      = a0 / cnt;
    yo[lane + 32] = a1 / cnt;
}

// ---------------------------------------------------------------------------
extern "C" void kernel_launch(void* const* d_in, const int* in_sizes, int n_in,
                              void* d_out, int out_size)
{
    const float* x      = (const float*)d_in[0];
    const float* W_attn = (const float*)d_in[1];
    const float* b_attn = (const float*)d_in[2];
    const float* W_proj = (const float*)d_in[3];
    const float* b_proj = (const float*)d_in[4];
    float* out = (float*)d_out;

    const int nx  = BATCH*SEQ*CDIM;      // 1572864
    const int nwa = CDIM*3*CDIM;         // 1769472
    const int nwp = CDIM*CDIM;           // 589824

    // allow 61.5KB dynamic smem for the GEMM (idempotent; not an allocation)
    static int smem_set = 0;
    if (!smem_set) {
        cudaFuncSetAttribute(tf32_gemm,
                             cudaFuncAttributeMaxDynamicSharedMemorySize,
                             GEMM_SMEM);
        smem_set = 1;
    }

    split_kernel<<<(nx/4 + 255)/256, 256>>>(x, 0, nx);
    split_kernel<<<(nwa/4 + 255)/256, 256>>>(W_attn, 1, nwa);
    split_kernel<<<(nwp/4 + 255)/256, 256>>>(W_proj, 2, nwp);

    {   // QKV: [2048,768] @ [768,2304] -> scatter q/k/v (fp32)
        dim3 grid(3*CDIM/128, (BATCH*SEQ)/128);
        tf32_gemm<<<grid, 256, GEMM_SMEM>>>(b_attn, out, BATCH*SEQ, 3*CDIM, CDIM, 0);
    }
    {   // sim: S = Q K^T per head (lower-tri blocks)
        dim3 grid(4, 4, BH);
        sim_tf32<<<grid, 256>>>();
    }
    {   // DPP attention -> g_y
        dim3 grid(SEQ/DW, BH);
        dpp_kernel<<<grid, 32*DW>>>();
    }
    split_kernel<<<(nx/4 + 255)/256, 256>>>(nullptr, 3, nx);   // y -> yh/yl
    {   // Proj: [2048,768] @ [768,768] -> out
        dim3 grid(CDIM/128, (BATCH*SEQ)/128);
        tf32_gemm<<<grid, 256, GEMM_SMEM>>>(b_proj, out, BATCH*SEQ, CDIM, CDIM, 1);
    }
}

// round 9
// speedup vs baseline: 1.1354x; 1.1354x over previous
#include <cuda_runtime.h>
#include <cuda_bf16.h>
#include <math.h>
#include <float.h>

#define BATCH 4
#define SEQ   512
#define CDIM  768
#define NHEAD 12
#define HS    64
#define BH    (BATCH*NHEAD)      // 48
#define DW    4                  // warps (tokens) per dpp block

#define NX  (BATCH*SEQ*CDIM)     // 1572864
#define NWA (CDIM*3*CDIM)        // 1769472
#define NWP (CDIM*CDIM)          // 589824

// ---------------- device scratch (allocation forbidden) ----------------
__device__ float g_q  [BH*SEQ*HS];          // fp32 q (feeds sim)
__device__ float g_k  [BH*SEQ*HS];          // fp32 k (feeds sim + DPP gram)
__device__ float g_v  [BH*SEQ*HS];          // fp32 v
__device__ float g_sim[(size_t)BH*SEQ*SEQ]; // q_i . k_j

// tf32 split operands (stored as fp32 bit patterns)
__device__ float g_xh [NX],  g_xl [NX];
__device__ float g_Wah[NWA], g_Wal[NWA];
__device__ float g_Wph[NWP], g_Wpl[NWP];
__device__ float g_yh [NX],  g_yl [NX];     // written by dpp epilogue

// ---------------- helpers ----------------
__device__ __forceinline__ float tf32_rnd(float x)
{
    unsigned r;
    asm("cvt.rna.tf32.f32 %0, %1;" : "=r"(r) : "f"(x));
    return __uint_as_float(r);
}

__device__ __forceinline__ void mma_tf32(float* c, const float* a, float b0, float b1)
{
    asm volatile("mma.sync.aligned.m16n8k8.row.col.f32.tf32.tf32.f32 "
        "{%0,%1,%2,%3}, {%4,%5,%6,%7}, {%8,%9}, {%0,%1,%2,%3};"
        : "+f"(c[0]), "+f"(c[1]), "+f"(c[2]), "+f"(c[3])
        : "r"(__float_as_uint(a[0])), "r"(__float_as_uint(a[1])),
          "r"(__float_as_uint(a[2])), "r"(__float_as_uint(a[3])),
          "r"(__float_as_uint(b0)),   "r"(__float_as_uint(b1)));
}

__device__ __forceinline__ void cp16(unsigned dst, const float* src)
{
    asm volatile("cp.async.ca.shared.global [%0], [%1], 16;" :: "r"(dst), "l"(src));
}

// monotonic float<->u32 map: preserves total order, NaN maps above +inf
__device__ __forceinline__ unsigned fmap(float v)
{
    unsigned u = __float_as_uint(v);
    return (u & 0x80000000u) ? ~u : (u | 0x80000000u);
}
__device__ __forceinline__ float funmap(unsigned m)
{
    unsigned u = (m & 0x80000000u) ? (m ^ 0x80000000u) : ~m;
    return __uint_as_float(u);
}

// ---------------- fused split kernel: x, W_attn, W_proj -> tf32 hi/lo ------
__global__ __launch_bounds__(256)
void split3_kernel(const float* __restrict__ x, const float* __restrict__ wa,
                   const float* __restrict__ wp)
{
    int i = (blockIdx.x*256 + threadIdx.x) * 4;
    const float* s; float *hi, *lo; int off;
    if (i < NX)            { s = x;  hi = g_xh;  lo = g_xl;  off = i; }
    else if (i < NX+NWA)   { s = wa; hi = g_Wah; lo = g_Wal; off = i - NX; }
    else if (i < NX+NWA+NWP) { s = wp; hi = g_Wph; lo = g_Wpl; off = i - NX - NWA; }
    else return;
    float4 v = *(const float4*)(s + off);
    float4 h, l;
    h.x = tf32_rnd(v.x); l.x = tf32_rnd(v.x - h.x);
    h.y = tf32_rnd(v.y); l.y = tf32_rnd(v.y - h.y);
    h.z = tf32_rnd(v.z); l.z = tf32_rnd(v.z - h.z);
    h.w = tf32_rnd(v.w); l.w = tf32_rnd(v.w - h.w);
    *(float4*)&hi[off] = h;
    *(float4*)&lo[off] = l;
}

// ---------------- qkv scatter ----------------
__device__ __forceinline__ void scatter_qkv(int row, int gc, float v0, float v1)
{
    int sect = gc / CDIM;              // 0=q 1=k 2=v
    int cc = gc - sect*CDIM;
    int h = cc >> 6, dd = cc & 63;
    int bb = row >> 9, t = row & 511;
    size_t off = ((size_t)(bb*NHEAD + h)*SEQ + t)*HS + dd;
    float* dst = (sect == 0) ? g_q : (sect == 1 ? g_k : g_v);
    *(float2*)&dst[off] = make_float2(v0, v1);
}

// ---------------- 3xTF32 GEMM, cp.async 2-stage (round-7 proven) ----------
#define STG 5248

__global__ __launch_bounds__(256, 2)
void tf32_gemm(const float* __restrict__ bias, float* __restrict__ Cout,
               int M, int N, int K, int mode)
{
    __shared__ __align__(16) float sm[2*STG];

    const float *Ah, *Al, *Bh, *Bl;
    if (mode == 0) { Ah = g_xh; Al = g_xl; Bh = g_Wah; Bl = g_Wal; }
    else           { Ah = g_yh; Al = g_yl; Bh = g_Wph; Bl = g_Wpl; }

    const int tid = threadIdx.x, lane = tid & 31, wid = tid >> 5;
    const int bm = blockIdx.y, bn = blockIdx.x;
    const int wm = wid & 3, wn = wid >> 2;
    const int g = lane >> 2, t = lane & 3;

    const unsigned smbase = (unsigned)__cvta_generic_to_shared(sm);

    int aSp[2], aM[2], aKq[2], bSp[2], bK[2], bN4[2];
#pragma unroll
    for (int h = 0; h < 2; h++) {
        int id = tid + h*256;
        aSp[h] = id >> 8; int ra = id & 255; aM[h] = ra >> 1; aKq[h] = (ra & 1) * 4;
        bSp[h] = id >> 8; int rb = id & 255; bK[h] = rb >> 5; bN4[h] = (rb & 31) * 4;
    }

    float acc[2][8][4];
#pragma unroll
    for (int a = 0; a < 2; a++)
#pragma unroll
        for (int b = 0; b < 8; b++)
#pragma unroll
            for (int c = 0; c < 4; c++) acc[a][b][c] = 0.f;

    const int NC = K >> 3;

    auto issue = [&](int s, int k0) {
        unsigned base = smbase + (unsigned)(s*STG)*4u;
#pragma unroll
        for (int h = 0; h < 2; h++) {
            const float* srcA = (aSp[h] ? Al : Ah) + (size_t)(bm*128 + aM[h])*K + k0 + aKq[h];
            cp16(base + (unsigned)(aSp[h]*1536 + aM[h]*12 + aKq[h])*4u, srcA);
        }
#pragma unroll
        for (int h = 0; h < 2; h++) {
            const float* srcB = (bSp[h] ? Bl : Bh) + (size_t)(k0 + bK[h])*N + bn*128 + bN4[h];
            cp16(base + (unsigned)(3072 + bSp[h]*1088 + bK[h]*136 + bN4[h])*4u, srcB);
        }
        asm volatile("cp.async.commit_group;");
    };

    issue(0, 0);

    for (int c = 0; c < NC; c++) {
        if (c + 1 < NC) {
            issue((c+1) & 1, (c+1)*8);
            asm volatile("cp.async.wait_group 1;");
        } else {
            asm volatile("cp.async.wait_group 0;");
        }
        __syncthreads();

        const float* S = sm + (c & 1)*STG;

        float ah[2][4], al[2][4];
#pragma unroll
        for (int mt = 0; mt < 2; mt++) {
            int m0 = (wm*32 + mt*16 + g)*12 + t;
            ah[mt][0] = S[m0];          ah[mt][1] = S[m0 + 96];
            ah[mt][2] = S[m0 + 4];      ah[mt][3] = S[m0 + 100];
            al[mt][0] = S[1536 + m0];   al[mt][1] = S[1536 + m0 + 96];
            al[mt][2] = S[1536 + m0+4]; al[mt][3] = S[1536 + m0 + 100];
        }
        // B fragment register pipeline across the nt loop
        int nb0 = wn*64 + g;
        float bh0 = S[3072 + t*136 + nb0];
        float bh1 = S[3072 + (t+4)*136 + nb0];
        float bl0 = S[4160 + t*136 + nb0];
        float bl1 = S[4160 + (t+4)*136 + nb0];
#pragma unroll
        for (int nt = 0; nt < 8; nt++) {
            float cbh0 = bh0, cbh1 = bh1, cbl0 = bl0, cbl1 = bl1;
            if (nt < 7) {
                int nb = wn*64 + (nt+1)*8 + g;
                bh0 = S[3072 + t*136 + nb];
                bh1 = S[3072 + (t+4)*136 + nb];
                bl0 = S[4160 + t*136 + nb];
                bl1 = S[4160 + (t+4)*136 + nb];
            }
#pragma unroll
            for (int mt = 0; mt < 2; mt++) {
                mma_tf32(acc[mt][nt], ah[mt], cbh0, cbh1);
                mma_tf32(acc[mt][nt], ah[mt], cbl0, cbl1);
                mma_tf32(acc[mt][nt], al[mt], cbh0, cbh1);
            }
        }
        __syncthreads();
    }

    // epilogue
#pragma unroll
    for (int mt = 0; mt < 2; mt++) {
        int r0 = bm*128 + wm*32 + mt*16 + g;
#pragma unroll
        for (int nt = 0; nt < 8; nt++) {
            int gc = bn*128 + wn*64 + nt*8 + t*2;
            float b0 = bias[gc], b1 = bias[gc+1];
            float v00 = acc[mt][nt][0] + b0, v01 = acc[mt][nt][1] + b1;
            float v10 = acc[mt][nt][2] + b0, v11 = acc[mt][nt][3] + b1;
            if (mode == 1) {
                *(float2*)&Cout[(size_t)r0*N + gc]     = make_float2(v00, v01);
                *(float2*)&Cout[(size_t)(r0+8)*N + gc] = make_float2(v10, v11);
            } else {
                scatter_qkv(r0,     gc, v00, v01);
                scatter_qkv(r0 + 8, gc, v10, v11);
            }
        }
    }
}

// ---------------- sim: S = Q K^T per head, 3xTF32 (unchanged) -------------
#define APITCH 20
__global__ __launch_bounds__(256)
void sim_tf32()
{
    const int bm = blockIdx.y, bn = blockIdx.x;
    if (bn > bm) return;
    const int bh = blockIdx.z;

    __shared__ __align__(16) float Qs[2][128*APITCH];
    __shared__ __align__(16) float Ks[2][128*APITCH];

    const float* __restrict__ qb = g_q + (size_t)bh*SEQ*HS;
    const float* __restrict__ kb = g_k + (size_t)bh*SEQ*HS;

    const int tid = threadIdx.x, lane = tid & 31, wid = tid >> 5;
    const int wm = wid & 3, wn = wid >> 2;
    const int g = lane >> 2, t = lane & 3;

    float acc[2][8][4];
#pragma unroll
    for (int a = 0; a < 2; a++)
#pragma unroll
        for (int b = 0; b < 8; b++)
#pragma unroll
            for (int c = 0; c < 4; c++) acc[a][b][c] = 0.f;

    for (int d0 = 0; d0 < HS; d0 += 16) {
        if (d0 > 0) __syncthreads();
#pragma unroll
        for (int j = 0; j < 2; j++) {
            int id = tid*2 + j;
            int r = id >> 2, c = (id & 3)*4;
            float4 qv = *(const float4*)&qb[(size_t)(bm*128 + r)*HS + d0 + c];
            float4 kv = *(const float4*)&kb[(size_t)(bn*128 + r)*HS + d0 + c];
            float4 qh, ql, kh, kl;
            qh.x = tf32_rnd(qv.x); ql.x = tf32_rnd(qv.x - qh.x);
            qh.y = tf32_rnd(qv.y); ql.y = tf32_rnd(qv.y - qh.y);
            qh.z = tf32_rnd(qv.z); ql.z = tf32_rnd(qv.z - qh.z);
            qh.w = tf32_rnd(qv.w); ql.w = tf32_rnd(qv.w - qh.w);
            kh.x = tf32_rnd(kv.x); kl.x = tf32_rnd(kv.x - kh.x);
            kh.y = tf32_rnd(kv.y); kl.y = tf32_rnd(kv.y - kh.y);
            kh.z = tf32_rnd(kv.z); kl.z = tf32_rnd(kv.z - kh.z);
            kh.w = tf32_rnd(kv.w); kl.w = tf32_rnd(kv.w - kh.w);
            *(float4*)&Qs[0][r*APITCH + c] = qh;
            *(float4*)&Qs[1][r*APITCH + c] = ql;
            *(float4*)&Ks[0][r*APITCH + c] = kh;
            *(float4*)&Ks[1][r*APITCH + c] = kl;
        }
        __syncthreads();

#pragma unroll
        for (int ks = 0; ks < 16; ks += 8) {
            float ah[2][4], al[2][4];
#pragma unroll
            for (int mt = 0; mt < 2; mt++) {
                int m0 = (wm*32 + mt*16 + g)*APITCH + ks + t;
                int m1 = m0 + 8*APITCH;
                ah[mt][0] = Qs[0][m0];   ah[mt][1] = Qs[0][m1];
                ah[mt][2] = Qs[0][m0+4]; ah[mt][3] = Qs[0][m1+4];
                al[mt][0] = Qs[1][m0];   al[mt][1] = Qs[1][m1];
                al[mt][2] = Qs[1][m0+4]; al[mt][3] = Qs[1][m1+4];
            }
#pragma unroll
            for (int nt = 0; nt < 8; nt++) {
                int n0 = (wn*64 + nt*8 + g)*APITCH + ks + t;
                float bh0 = Ks[0][n0];
                float bh1 = Ks[0][n0+4];
                float bl0 = Ks[1][n0];
                float bl1 = Ks[1][n0+4];
#pragma unroll
                for (int mt = 0; mt < 2; mt++) {
                    mma_tf32(acc[mt][nt], ah[mt], bh0, bh1);
                    mma_tf32(acc[mt][nt], ah[mt], bl0, bl1);
                    mma_tf32(acc[mt][nt], al[mt], bh0, bh1);
                }
            }
        }
    }

    float* S = g_sim + (size_t)bh*SEQ*SEQ;
#pragma unroll
    for (int mt = 0; mt < 2; mt++) {
        int r0 = bm*128 + wm*32 + mt*16 + g;
#pragma unroll
        for (int nt = 0; nt < 8; nt++) {
            int gc = bn*128 + wn*64 + nt*8 + t*2;
            *(float2*)&S[(size_t)r0*SEQ + gc]     = make_float2(acc[mt][nt][0], acc[mt][nt][1]);
            *(float2*)&S[(size_t)(r0+8)*SEQ + gc] = make_float2(acc[mt][nt][2], acc[mt][nt][3]);
        }
    }
}

// ---------------- DPP greedy selection: redux-based argmax ----------------
__global__ __launch_bounds__(32*DW)
void dpp_kernel()
{
    __shared__ __align__(16) float krows[DW][17][68];
    __shared__ float Gm[DW][17][17];

    const unsigned FULL = 0xffffffffu;
    const int lane = threadIdx.x & 31;
    const int wrp  = threadIdx.x >> 5;
    const int i  = blockIdx.x * DW + wrp;
    const int bh = blockIdx.y;
    const int nvalid = i + 1;

    const float* __restrict__ kb = g_k + (size_t)bh*SEQ*HS;
    const float* __restrict__ vb = g_v + (size_t)bh*SEQ*HS;
    const float* __restrict__ simRow = g_sim + ((size_t)bh*SEQ + i)*SEQ;

    // ---- lane-major sim load: val[c] = sim[lane*16 + c] ----
    float val[16];
    {
        const float4* sr = (const float4*)simRow;
#pragma unroll
        for (int q = 0; q < 4; q++) {
            float4 v4 = sr[lane*4 + q];
            val[q*4+0] = v4.x; val[q*4+1] = v4.y;
            val[q*4+2] = v4.z; val[q*4+3] = v4.w;
        }
        int base = lane*16;
#pragma unroll
        for (int c = 0; c < 16; c++)
            if (base + c >= nvalid) val[c] = -INFINITY;
    }

    // local best (lowest c wins ties -> lowest global idx within lane)
    float bv = val[0]; int bc = 0;
#pragma unroll
    for (int c = 1; c < 16; c++) if (val[c] > bv) { bv = val[c]; bc = c; }

    // ---- top-16 via redux.max (lowest set lane = lowest global idx) ----
    float myVal = -INFINITY; int myIdx = i;   // lane t (<16) ends owning top-t
    for (int t = 0; t < 16; t++) {
        unsigned m = fmap(bv);
        unsigned mmax = __reduce_max_sync(FULL, m);
        unsigned ball = __ballot_sync(FULL, m == mmax);
        int wl = __ffs(ball) - 1;
        int wc = __shfl_sync(FULL, bc, wl);
        if (lane == t) { myVal = funmap(mmax); myIdx = wl*16 + wc; }
        if (lane == wl) {
#pragma unroll
            for (int c = 0; c < 16; c++) if (c == wc) val[c] = -INFINITY;
            bv = val[0]; bc = 0;
#pragma unroll
            for (int c = 1; c < 16; c++) if (val[c] > bv) { bv = val[c]; bc = c; }
        }
    }
    bool availb = (lane < 16) && (myVal > -INFINITY) && (myIdx != i);
    unsigned avail = __ballot_sync(FULL, availb) & 0xFFFFu;
    int safeIdx = (lane < 16 && myVal > -INFINITY) ? myIdx : i;

    // ---- stage 17 k-rows (cand 0..15, then i) into padded smem ----
    const int half = lane >> 4;
    const int hl   = lane & 15;
    for (int r = 0; r < 17; r += 2) {
        int src = r + half;
        int sl  = src & 15;
        int gv  = __shfl_sync(FULL, safeIdx, sl);
        int gidx = (src >= 16) ? i : gv;
        if (src <= 16) {
            float4 kv = ((const float4*)(kb + (size_t)gidx*HS))[hl];
            *(float4*)&krows[wrp][src][hl*4] = kv;
        }
    }
    __syncwarp();

    // ---- 17x17 Gram from smem (symmetric halves) ----
#pragma unroll
    for (int t = 0; t < 10; t++) {
        int e = lane + 32*t;
        if (e < 289) {
            int a = e / 17, b = e - a*17;
            if (a <= b) {
                const float* ra = krows[wrp][a];
                const float* rb = krows[wrp][b];
                float acc = 0.f;
#pragma unroll
                for (int c = 0; c < 16; c++) {
                    float4 x = ((const float4*)ra)[c];
                    float4 y = ((const float4*)rb)[c];
                    acc = fmaf(x.x, y.x, acc);
                    acc = fmaf(x.y, y.y, acc);
                    acc = fmaf(x.z, y.z, acc);
                    acc = fmaf(x.w, y.w, acc);
                }
                Gm[wrp][a][b] = acc;
                Gm[wrp][b][a] = acc;
            }
        }
    }
    __syncwarp();

    // ---- greedy loop with incremental Cholesky ----
    const int cl = lane & 15;
    float Gii  = Gm[wrp][16][16];
    float detS = Gii;
    float curS = -logf(Gii + 1e-6f);
    int count = 1;
    float w[8];
    float w0 = Gm[wrp][cl][16] / sqrtf(Gii);
    w[0] = w0;
#pragma unroll
    for (int j = 1; j < 8; j++) w[j] = 0.f;
    float ec = Gm[wrp][cl][cl] - w0*w0;
    int selTok[8];
#pragma unroll
    for (int j = 0; j < 8; j++) selTok[j] = i;

    for (int step = 0; step < 7; step++) {
        bool av = (lane < 16) && ((avail >> lane) & 1u);
        float s = av ? (-logf(detS*ec + 1e-6f) / (float)(count + 1)) : -INFINITY;
        // argmax: NaN is max; first (lowest) candidate slot wins ties
        unsigned m = fmap(s);
        unsigned mmax = __reduce_max_sync(FULL, m);
        unsigned ball = __ballot_sync(FULL, m == mmax);
        int bl = __ffs(ball) - 1;
        float bs = funmap(mmax);

        bool anyAvail = (avail != 0u);
        bool accept = anyAvail && ((bs > curS) || (count < 2));
        if (!accept) break;   // warp-uniform

        float eb = __shfl_sync(FULL, ec, bl);
        float Lb = sqrtf(eb);
        float dot = 0.f;
#pragma unroll
        for (int j = 0; j < 7; j++) {
            float wbj = __shfl_sync(FULL, w[j], bl);
            if (j < count) dot += w[j]*wbj;
        }
        float wn = (Gm[wrp][cl][bl] - dot) / Lb;
#pragma unroll
        for (int j = 1; j < 8; j++) if (j == count) w[j] = wn;
        ec -= wn*wn;
        detS *= eb;
        curS = bs;
        int btok = __shfl_sync(FULL, myIdx, bl);
#pragma unroll
        for (int j = 1; j < 8; j++) if (j == count) selTok[j] = btok;
        count++;
        avail &= ~(1u << bl);
    }

    // ---- y_i = mean of selected v rows; write tf32 hi/lo directly ----
    float a0 = 0.f, a1 = 0.f;
#pragma unroll
    for (int r = 0; r < 8; r++) {
        if (r < count) {
            const float* vr = vb + (size_t)selTok[r]*HS;
            a0 += vr[lane];
            a1 += vr[lane + 32];
        }
    }
    float cnt = (float)count;
    float o0 = a0 / cnt, o1 = a1 / cnt;
    int bb = bh / NHEAD, h = bh % NHEAD;
    size_t yoff = ((size_t)(bb*SEQ + i))*CDIM + h*HS;
    float h0 = tf32_rnd(o0), l0 = tf32_rnd(o0 - h0);
    float h1 = tf32_rnd(o1), l1 = tf32_rnd(o1 - h1);
    g_yh[yoff + lane]      = h0;  g_yl[yoff + lane]      = l0;
    g_yh[yoff + lane + 32] = h1;  g_yl[yoff + lane + 32] = l1;
}

// ---------------------------------------------------------------------------
extern "C" void kernel_launch(void* const* d_in, const int* in_sizes, int n_in,
                              void* d_out, int out_size)
{
    const float* x      = (const float*)d_in[0];
    const float* W_attn = (const float*)d_in[1];
    const float* b_attn = (const float*)d_in[2];
    const float* W_proj = (const float*)d_in[3];
    const float* b_proj = (const float*)d_in[4];
    float* out = (float*)d_out;

    const int ntot = NX + NWA + NWP;
    split3_kernel<<<(ntot/4 + 255)/256, 256>>>(x, W_attn, W_proj);

    {   // QKV: [2048,768] @ [768,2304] -> scatter q/k/v (fp32)
        dim3 grid(3*CDIM/128, (BATCH*SEQ)/128);
        tf32_gemm<<<grid, 256>>>(b_attn, out, BATCH*SEQ, 3*CDIM, CDIM, 0);
    }
    {   // sim: S = Q K^T per head (lower-tri blocks)
        dim3 grid(4, 4, BH);
        sim_tf32<<<grid, 256>>>();
    }
    {   // DPP attention -> g_yh/g_yl
        dim3 grid(SEQ/DW, BH);
        dpp_kernel<<<grid, 32*DW>>>();
    }
    {   // Proj: [2048,768] @ [768,768] -> out
        dim3 grid(CDIM/128, (BATCH*SEQ)/128);
        tf32_gemm<<<grid, 256>>>(b_proj, out, BATCH*SEQ, CDIM, CDIM, 1);
    }
}

// round 11
// speedup vs baseline: 1.2824x; 1.1294x over previous
#include <cuda_runtime.h>
#include <cuda_bf16.h>
#include <math.h>
#include <float.h>

#define BATCH 4
#define SEQ   512
#define CDIM  768
#define NHEAD 12
#define HS    64
#define BH    (BATCH*NHEAD)      // 48
#define DW    4                  // warps (tokens) per dpp block

#define NX  (BATCH*SEQ*CDIM)     // 1572864
#define NWA (CDIM*3*CDIM)        // 1769472
#define NWP (CDIM*CDIM)          // 589824

// ---------------- device scratch (allocation forbidden) ----------------
__device__ float g_q  [BH*SEQ*HS];
__device__ float g_k  [BH*SEQ*HS];
__device__ float g_v  [BH*SEQ*HS];
__device__ float g_sim[(size_t)BH*SEQ*SEQ];

// tf32 split operands (fp32 bit patterns)
__device__ float g_xh [NX],  g_xl [NX];
__device__ float g_Wah[NWA], g_Wal[NWA];
__device__ float g_Wph[NWP], g_Wpl[NWP];
__device__ float g_yh [NX],  g_yl [NX];     // written by dpp epilogue

// ---------------- helpers ----------------
__device__ __forceinline__ float tf32_rnd(float x)
{
    unsigned r;
    asm("cvt.rna.tf32.f32 %0, %1;" : "=r"(r) : "f"(x));
    return __uint_as_float(r);
}

__device__ __forceinline__ void mma_tf32(float* c, const float* a, float b0, float b1)
{
    asm volatile("mma.sync.aligned.m16n8k8.row.col.f32.tf32.tf32.f32 "
        "{%0,%1,%2,%3}, {%4,%5,%6,%7}, {%8,%9}, {%0,%1,%2,%3};"
        : "+f"(c[0]), "+f"(c[1]), "+f"(c[2]), "+f"(c[3])
        : "r"(__float_as_uint(a[0])), "r"(__float_as_uint(a[1])),
          "r"(__float_as_uint(a[2])), "r"(__float_as_uint(a[3])),
          "r"(__float_as_uint(b0)),   "r"(__float_as_uint(b1)));
}

__device__ __forceinline__ void cp16(unsigned dst, const float* src)
{
    asm volatile("cp.async.ca.shared.global [%0], [%1], 16;" :: "r"(dst), "l"(src));
}

// monotonic float<->u32 map: preserves total order, NaN maps above +inf
__device__ __forceinline__ unsigned fmap(float v)
{
    unsigned u = __float_as_uint(v);
    return (u & 0x80000000u) ? ~u : (u | 0x80000000u);
}
__device__ __forceinline__ float funmap(unsigned m)
{
    unsigned u = (m & 0x80000000u) ? (m ^ 0x80000000u) : ~m;
    return __uint_as_float(u);
}

// ---------------- fused split kernel: x, W_attn, W_proj -> tf32 hi/lo ------
__global__ __launch_bounds__(256)
void split3_kernel(const float* __restrict__ x, const float* __restrict__ wa,
                   const float* __restrict__ wp)
{
    int i = (blockIdx.x*256 + threadIdx.x) * 4;
    const float* s; float *hi, *lo; int off;
    if (i < NX)              { s = x;  hi = g_xh;  lo = g_xl;  off = i; }
    else if (i < NX+NWA)     { s = wa; hi = g_Wah; lo = g_Wal; off = i - NX; }
    else if (i < NX+NWA+NWP) { s = wp; hi = g_Wph; lo = g_Wpl; off = i - NX - NWA; }
    else return;
    float4 v = *(const float4*)(s + off);
    float4 h, l;
    h.x = tf32_rnd(v.x); l.x = tf32_rnd(v.x - h.x);
    h.y = tf32_rnd(v.y); l.y = tf32_rnd(v.y - h.y);
    h.z = tf32_rnd(v.z); l.z = tf32_rnd(v.z - h.z);
    h.w = tf32_rnd(v.w); l.w = tf32_rnd(v.w - h.w);
    *(float4*)&hi[off] = h;
    *(float4*)&lo[off] = l;
}

// ---------------- qkv scatter ----------------
__device__ __forceinline__ void scatter_qkv(int row, int gc, float v0, float v1)
{
    int sect = gc / CDIM;              // 0=q 1=k 2=v
    int cc = gc - sect*CDIM;
    int h = cc >> 6, dd = cc & 63;
    int bb = row >> 9, t = row & 511;
    size_t off = ((size_t)(bb*NHEAD + h)*SEQ + t)*HS + dd;
    float* dst = (sect == 0) ? g_q : (sect == 1 ? g_k : g_v);
    *(float2*)&dst[off] = make_float2(v0, v1);
}

// ---------------- 3xTF32 GEMM, cp.async 2-stage, K-chunk 16 ----------------
// Stage layout (float indices):
//   Ah: [0,2560)      (128 rows x pitch 20)
//   Al: [2560,5120)
//   Bh: [5120,7296)   (16 k-rows x pitch 136)
//   Bl: [7296,9472)
#define STGF 9472
#define GEMM_SMEM (2*STGF*4)

__global__ __launch_bounds__(256, 2)
void tf32_gemm(const float* __restrict__ bias, float* __restrict__ Cout,
               int M, int N, int K, int mode)
{
    extern __shared__ __align__(16) float sm[];

    const float *Ah, *Al, *Bh, *Bl;
    if (mode == 0) { Ah = g_xh; Al = g_xl; Bh = g_Wah; Bl = g_Wal; }
    else           { Ah = g_yh; Al = g_yl; Bh = g_Wph; Bl = g_Wpl; }

    const int tid = threadIdx.x, lane = tid & 31, wid = tid >> 5;
    const int bm = blockIdx.y, bn = blockIdx.x;
    const int wm = wid & 3, wn = wid >> 2;
    const int g = lane >> 2, t = lane & 3;

    const unsigned smbase = (unsigned)__cvta_generic_to_shared(sm);

    float acc[2][8][4];
#pragma unroll
    for (int a = 0; a < 2; a++)
#pragma unroll
        for (int b = 0; b < 8; b++)
#pragma unroll
            for (int c = 0; c < 4; c++) acc[a][b][c] = 0.f;

    const int NC = K >> 4;   // K-chunk 16

    auto issue = [&](int s, int k0) {
        unsigned base = smbase + (unsigned)(s*STGF)*4u;
        // A: 2 splits x 128 rows x 4 quads = 1024 -> 4/thread
#pragma unroll
        for (int j = 0; j < 4; j++) {
            int id = tid + 256*j;
            int sp = id >> 9, rem = id & 511, row = rem >> 2, q = (rem & 3)*4;
            const float* src = (sp ? Al : Ah) + (size_t)(bm*128 + row)*K + k0 + q;
            cp16(base + (unsigned)(sp*2560 + row*20 + q)*4u, src);
        }
        // B: 2 splits x 16 k-rows x 32 quads = 1024 -> 4/thread
#pragma unroll
        for (int j = 0; j < 4; j++) {
            int id = tid + 256*j;
            int sp = id >> 9, rem = id & 511, kr = rem >> 5, nq = (rem & 31)*4;
            const float* src = (sp ? Bl : Bh) + (size_t)(k0 + kr)*N + bn*128 + nq;
            cp16(base + (unsigned)(5120 + sp*2176 + kr*136 + nq)*4u, src);
        }
        asm volatile("cp.async.commit_group;");
    };

    issue(0, 0);

    for (int c = 0; c < NC; c++) {
        if (c + 1 < NC) {
            issue((c+1) & 1, (c+1)*16);
            asm volatile("cp.async.wait_group 1;");
        } else {
            asm volatile("cp.async.wait_group 0;");
        }
        __syncthreads();

        const float* S = sm + (c & 1)*STGF;

#pragma unroll
        for (int ks = 0; ks < 16; ks += 8) {
            float ah[2][4], al[2][4];
#pragma unroll
            for (int mt = 0; mt < 2; mt++) {
                int m0 = (wm*32 + mt*16 + g)*20 + ks + t;
                ah[mt][0] = S[m0];          ah[mt][1] = S[m0 + 160];   // +8 rows
                ah[mt][2] = S[m0 + 4];      ah[mt][3] = S[m0 + 164];
                al[mt][0] = S[2560 + m0];   al[mt][1] = S[2560 + m0 + 160];
                al[mt][2] = S[2560 + m0+4]; al[mt][3] = S[2560 + m0 + 164];
            }
            // B fragment register pipeline across the nt loop
            int nb0 = wn*64 + g;
            float bh0 = S[5120 + (ks+t)*136 + nb0];
            float bh1 = S[5120 + (ks+t+4)*136 + nb0];
            float bl0 = S[7296 + (ks+t)*136 + nb0];
            float bl1 = S[7296 + (ks+t+4)*136 + nb0];
#pragma unroll
            for (int nt = 0; nt < 8; nt++) {
                float cbh0 = bh0, cbh1 = bh1, cbl0 = bl0, cbl1 = bl1;
                if (nt < 7) {
                    int nb = wn*64 + (nt+1)*8 + g;
                    bh0 = S[5120 + (ks+t)*136 + nb];
                    bh1 = S[5120 + (ks+t+4)*136 + nb];
                    bl0 = S[7296 + (ks+t)*136 + nb];
                    bl1 = S[7296 + (ks+t+4)*136 + nb];
                }
#pragma unroll
                for (int mt = 0; mt < 2; mt++) {
                    mma_tf32(acc[mt][nt], ah[mt], cbh0, cbh1);
                    mma_tf32(acc[mt][nt], ah[mt], cbl0, cbl1);
                    mma_tf32(acc[mt][nt], al[mt], cbh0, cbh1);
                }
            }
        }
        __syncthreads();
    }

    // epilogue
#pragma unroll
    for (int mt = 0; mt < 2; mt++) {
        int r0 = bm*128 + wm*32 + mt*16 + g;
#pragma unroll
        for (int nt = 0; nt < 8; nt++) {
            int gc = bn*128 + wn*64 + nt*8 + t*2;
            float b0 = bias[gc], b1 = bias[gc+1];
            float v00 = acc[mt][nt][0] + b0, v01 = acc[mt][nt][1] + b1;
            float v10 = acc[mt][nt][2] + b0, v11 = acc[mt][nt][3] + b1;
            if (mode == 1) {
                *(float2*)&Cout[(size_t)r0*N + gc]     = make_float2(v00, v01);
                *(float2*)&Cout[(size_t)(r0+8)*N + gc] = make_float2(v10, v11);
            } else {
                scatter_qkv(r0,     gc, v00, v01);
                scatter_qkv(r0 + 8, gc, v10, v11);
            }
        }
    }
}

// ---------------- sim: S = Q K^T per head, 3xTF32 (proven) ----------------
#define APITCH 20
__global__ __launch_bounds__(256)
void sim_tf32()
{
    const int bm = blockIdx.y, bn = blockIdx.x;
    if (bn > bm) return;
    const int bh = blockIdx.z;

    __shared__ __align__(16) float Qs[2][128*APITCH];
    __shared__ __align__(16) float Ks[2][128*APITCH];

    const float* __restrict__ qb = g_q + (size_t)bh*SEQ*HS;
    const float* __restrict__ kb = g_k + (size_t)bh*SEQ*HS;

    const int tid = threadIdx.x, lane = tid & 31, wid = tid >> 5;
    const int wm = wid & 3, wn = wid >> 2;
    const int g = lane >> 2, t = lane & 3;

    float acc[2][8][4];
#pragma unroll
    for (int a = 0; a < 2; a++)
#pragma unroll
        for (int b = 0; b < 8; b++)
#pragma unroll
            for (int c = 0; c < 4; c++) acc[a][b][c] = 0.f;

    for (int d0 = 0; d0 < HS; d0 += 16) {
        if (d0 > 0) __syncthreads();
#pragma unroll
        for (int j = 0; j < 2; j++) {
            int id = tid*2 + j;
            int r = id >> 2, c = (id & 3)*4;
            float4 qv = *(const float4*)&qb[(size_t)(bm*128 + r)*HS + d0 + c];
            float4 kv = *(const float4*)&kb[(size_t)(bn*128 + r)*HS + d0 + c];
            float4 qh, ql, kh, kl;
            qh.x = tf32_rnd(qv.x); ql.x = tf32_rnd(qv.x - qh.x);
            qh.y = tf32_rnd(qv.y); ql.y = tf32_rnd(qv.y - qh.y);
            qh.z = tf32_rnd(qv.z); ql.z = tf32_rnd(qv.z - qh.z);
            qh.w = tf32_rnd(qv.w); ql.w = tf32_rnd(qv.w - qh.w);
            kh.x = tf32_rnd(kv.x); kl.x = tf32_rnd(kv.x - kh.x);
            kh.y = tf32_rnd(kv.y); kl.y = tf32_rnd(kv.y - kh.y);
            kh.z = tf32_rnd(kv.z); kl.z = tf32_rnd(kv.z - kh.z);
            kh.w = tf32_rnd(kv.w); kl.w = tf32_rnd(kv.w - kh.w);
            *(float4*)&Qs[0][r*APITCH + c] = qh;
            *(float4*)&Qs[1][r*APITCH + c] = ql;
            *(float4*)&Ks[0][r*APITCH + c] = kh;
            *(float4*)&Ks[1][r*APITCH + c] = kl;
        }
        __syncthreads();

#pragma unroll
        for (int ks = 0; ks < 16; ks += 8) {
            float ah[2][4], al[2][4];
#pragma unroll
            for (int mt = 0; mt < 2; mt++) {
                int m0 = (wm*32 + mt*16 + g)*APITCH + ks + t;
                int m1 = m0 + 8*APITCH;
                ah[mt][0] = Qs[0][m0];   ah[mt][1] = Qs[0][m1];
                ah[mt][2] = Qs[0][m0+4]; ah[mt][3] = Qs[0][m1+4];
                al[mt][0] = Qs[1][m0];   al[mt][1] = Qs[1][m1];
                al[mt][2] = Qs[1][m0+4]; al[mt][3] = Qs[1][m1+4];
            }
#pragma unroll
            for (int nt = 0; nt < 8; nt++) {
                int n0 = (wn*64 + nt*8 + g)*APITCH + ks + t;
                float bh0 = Ks[0][n0];
                float bh1 = Ks[0][n0+4];
                float bl0 = Ks[1][n0];
                float bl1 = Ks[1][n0+4];
#pragma unroll
                for (int mt = 0; mt < 2; mt++) {
                    mma_tf32(acc[mt][nt], ah[mt], bh0, bh1);
                    mma_tf32(acc[mt][nt], ah[mt], bl0, bl1);
                    mma_tf32(acc[mt][nt], al[mt], bh0, bh1);
                }
            }
        }
    }

    float* S = g_sim + (size_t)bh*SEQ*SEQ;
#pragma unroll
    for (int mt = 0; mt < 2; mt++) {
        int r0 = bm*128 + wm*32 + mt*16 + g;
#pragma unroll
        for (int nt = 0; nt < 8; nt++) {
            int gc = bn*128 + wn*64 + nt*8 + t*2;
            *(float2*)&S[(size_t)r0*SEQ + gc]     = make_float2(acc[mt][nt][0], acc[mt][nt][1]);
            *(float2*)&S[(size_t)(r0+8)*SEQ + gc] = make_float2(acc[mt][nt][2], acc[mt][nt][3]);
        }
    }
}

// ---------------- DPP: dead-mask + lazy top-2 argmax ----------------------
__global__ __launch_bounds__(32*DW)
void dpp_kernel()
{
    __shared__ __align__(16) float krows[DW][17][68];
    __shared__ float Gm[DW][17][17];

    const unsigned FULL = 0xffffffffu;
    const int lane = threadIdx.x & 31;
    const int wrp  = threadIdx.x >> 5;
    const int i  = blockIdx.x * DW + wrp;
    const int bh = blockIdx.y;
    const int nvalid = i + 1;

    const float* __restrict__ kb = g_k + (size_t)bh*SEQ*HS;
    const float* __restrict__ vb = g_v + (size_t)bh*SEQ*HS;
    const float* __restrict__ simRow = g_sim + ((size_t)bh*SEQ + i)*SEQ;

    // ---- lane-major sim load: val[c] = sim[lane*16 + c] ----
    float val[16];
    {
        const float4* sr = (const float4*)simRow;
#pragma unroll
        for (int q = 0; q < 4; q++) {
            float4 v4 = sr[lane*4 + q];
            val[q*4+0] = v4.x; val[q*4+1] = v4.y;
            val[q*4+2] = v4.z; val[q*4+3] = v4.w;
        }
    }
    // dead mask: bits for c >= valid count in this lane
    int cnt = nvalid - lane*16;
    cnt = (cnt < 0) ? 0 : (cnt > 16 ? 16 : cnt);
    unsigned dead = (0xFFFFu << cnt) & 0xFFFFu;

    // initial local top-2 (strict > keeps lowest c for both)
    float bv1 = -INFINITY, bv2 = -INFINITY; int bc1 = 0, bc2 = 0;
#pragma unroll
    for (int c = 0; c < 16; c++) {
        float v = ((dead >> c) & 1u) ? -INFINITY : val[c];
        if (v > bv1)      { bv2 = bv1; bc2 = bc1; bv1 = v; bc1 = c; }
        else if (v > bv2) { bv2 = v; bc2 = c; }
    }
    bool have2 = true;

    // ---- top-16 extraction ----
    float myVal = -INFINITY; int myIdx = i;   // lane t (<16) ends owning top-t
    for (int t = 0; t < 16; t++) {
        unsigned m = fmap(bv1);
        unsigned mmax = __reduce_max_sync(FULL, m);
        unsigned ball = __ballot_sync(FULL, m == mmax);
        int wl = __ffs(ball) - 1;
        int wc = __shfl_sync(FULL, bc1, wl);
        if (lane == t) { myVal = funmap(mmax); myIdx = wl*16 + wc; }
        if (lane == wl) {
            dead |= 1u << bc1;
            if (have2) {
                bv1 = bv2; bc1 = bc2; have2 = false;
            } else {
                bv1 = -INFINITY; bc1 = 0; bv2 = -INFINITY; bc2 = 0;
#pragma unroll
                for (int c = 0; c < 16; c++) {
                    float v = ((dead >> c) & 1u) ? -INFINITY : val[c];
                    if (v > bv1)      { bv2 = bv1; bc2 = bc1; bv1 = v; bc1 = c; }
                    else if (v > bv2) { bv2 = v; bc2 = c; }
                }
                have2 = true;
            }
        }
    }
    bool availb = (lane < 16) && (myVal > -INFINITY) && (myIdx != i);
    unsigned avail = __ballot_sync(FULL, availb) & 0xFFFFu;
    int safeIdx = (lane < 16 && myVal > -INFINITY) ? myIdx : i;

    // ---- stage 17 k-rows (cand 0..15, then i) into padded smem ----
    const int half = lane >> 4;
    const int hl   = lane & 15;
    for (int r = 0; r < 17; r += 2) {
        int src = r + half;
        int sl  = src & 15;
        int gv  = __shfl_sync(FULL, safeIdx, sl);
        int gidx = (src >= 16) ? i : gv;
        if (src <= 16) {
            float4 kv = ((const float4*)(kb + (size_t)gidx*HS))[hl];
            *(float4*)&krows[wrp][src][hl*4] = kv;
        }
    }
    __syncwarp();

    // ---- 17x17 Gram from smem (symmetric halves) ----
#pragma unroll
    for (int t = 0; t < 10; t++) {
        int e = lane + 32*t;
        if (e < 289) {
            int a = e / 17, b = e - a*17;
            if (a <= b) {
                const float* ra = krows[wrp][a];
                const float* rb = krows[wrp][b];
                float acc = 0.f;
#pragma unroll
                for (int c = 0; c < 16; c++) {
                    float4 x = ((const float4*)ra)[c];
                    float4 y = ((const float4*)rb)[c];
                    acc = fmaf(x.x, y.x, acc);
                    acc = fmaf(x.y, y.y, acc);
                    acc = fmaf(x.z, y.z, acc);
                    acc = fmaf(x.w, y.w, acc);
                }
                Gm[wrp][a][b] = acc;
                Gm[wrp][b][a] = acc;
            }
        }
    }
    __syncwarp();

    // ---- greedy loop with incremental Cholesky ----
    const int cl = lane & 15;
    float Gii  = Gm[wrp][16][16];
    float detS = Gii;
    float curS = -logf(Gii + 1e-6f);
    int count = 1;
    float w[8];
    float w0 = Gm[wrp][cl][16] / sqrtf(Gii);
    w[0] = w0;
#pragma unroll
    for (int j = 1; j < 8; j++) w[j] = 0.f;
    float ec = Gm[wrp][cl][cl] - w0*w0;
    int selTok[8];
#pragma unroll
    for (int j = 0; j < 8; j++) selTok[j] = i;

    for (int step = 0; step < 7; step++) {
        bool av = (lane < 16) && ((avail >> lane) & 1u);
        float s = av ? (-logf(detS*ec + 1e-6f) / (float)(count + 1)) : -INFINITY;
        unsigned m = fmap(s);
        unsigned mmax = __reduce_max_sync(FULL, m);
        unsigned ball = __ballot_sync(FULL, m == mmax);
        int bl = __ffs(ball) - 1;
        float bs = funmap(mmax);

        bool anyAvail = (avail != 0u);
        bool accept = anyAvail && ((bs > curS) || (count < 2));
        if (!accept) break;

        float eb = __shfl_sync(FULL, ec, bl);
        float Lb = sqrtf(eb);
        float dot = 0.f;
#pragma unroll
        for (int j = 0; j < 7; j++) {
            float wbj = __shfl_sync(FULL, w[j], bl);
            if (j < count) dot += w[j]*wbj;
        }
        float wn = (Gm[wrp][cl][bl] - dot) / Lb;
#pragma unroll
        for (int j = 1; j < 8; j++) if (j == count) w[j] = wn;
        ec -= wn*wn;
        detS *= eb;
        curS = bs;
        int btok = __shfl_sync(FULL, myIdx, bl);
#pragma unroll
        for (int j = 1; j < 8; j++) if (j == count) selTok[j] = btok;
        count++;
        avail &= ~(1u << bl);
    }

    // ---- y_i = mean of selected v rows; write tf32 hi/lo directly ----
    float a0 = 0.f, a1 = 0.f;
#pragma unroll
    for (int r = 0; r < 8; r++) {
        if (r < count) {
            const float* vr = vb + (size_t)selTok[r]*HS;
            a0 += vr[lane];
            a1 += vr[lane + 32];
        }
    }
    float cnt2 = (float)count;
    float o0 = a0 / cnt2, o1 = a1 / cnt2;
    int bb = bh / NHEAD, h = bh % NHEAD;
    size_t yoff = ((size_t)(bb*SEQ + i))*CDIM + h*HS;
    float h0 = tf32_rnd(o0), l0 = tf32_rnd(o0 - h0);
    float h1 = tf32_rnd(o1), l1 = tf32_rnd(o1 - h1);
    g_yh[yoff + lane]      = h0;  g_yl[yoff + lane]      = l0;
    g_yh[yoff + lane + 32] = h1;  g_yl[yoff + lane + 32] = l1;
}

// ---------------------------------------------------------------------------
extern "C" void kernel_launch(void* const* d_in, const int* in_sizes, int n_in,
                              void* d_out, int out_size)
{
    const float* x      = (const float*)d_in[0];
    const float* W_attn = (const float*)d_in[1];
    const float* b_attn = (const float*)d_in[2];
    const float* W_proj = (const float*)d_in[3];
    const float* b_proj = (const float*)d_in[4];
    float* out = (float*)d_out;

    static int smem_set = 0;
    if (!smem_set) {
        cudaFuncSetAttribute(tf32_gemm,
                             cudaFuncAttributeMaxDynamicSharedMemorySize,
                             GEMM_SMEM);
        smem_set = 1;
    }

    const int ntot = NX + NWA + NWP;
    split3_kernel<<<(ntot/4 + 255)/256, 256>>>(x, W_attn, W_proj);

    {   // QKV: [2048,768] @ [768,2304] -> scatter q/k/v (fp32)
        dim3 grid(3*CDIM/128, (BATCH*SEQ)/128);
        tf32_gemm<<<grid, 256, GEMM_SMEM>>>(b_attn, out, BATCH*SEQ, 3*CDIM, CDIM, 0);
    }
    {   // sim: S = Q K^T per head (lower-tri blocks)
        dim3 grid(4, 4, BH);
        sim_tf32<<<grid, 256>>>();
    }
    {   // DPP attention -> g_yh/g_yl
        dim3 grid(SEQ/DW, BH);
        dpp_kernel<<<grid, 32*DW>>>();
    }
    {   // Proj: [2048,768] @ [768,768] -> out
        dim3 grid(CDIM/128, (BATCH*SEQ)/128);
        tf32_gemm<<<grid, 256, GEMM_SMEM>>>(b_proj, out, BATCH*SEQ, CDIM, CDIM, 1);
    }
}

// round 12
// speedup vs baseline: 1.3153x; 1.0256x over previous
#include <cuda_runtime.h>
#include <cuda_bf16.h>
#include <math.h>
#include <float.h>

#define BATCH 4
#define SEQ   512
#define CDIM  768
#define NHEAD 12
#define HS    64
#define BH    (BATCH*NHEAD)      // 48
#define DW    4                  // warps (tokens) per dpp block

#define NX  (BATCH*SEQ*CDIM)     // 1572864
#define NWA (CDIM*3*CDIM)        // 1769472
#define NWP (CDIM*CDIM)          // 589824

// ---------------- device scratch (allocation forbidden) ----------------
__device__ float g_q   [BH*SEQ*HS];
__device__ float g_k   [BH*SEQ*HS];
__device__ float g_v   [BH*SEQ*HS];
__device__ float g_sim [(size_t)BH*SEQ*SEQ];   // q_i . k_j   (lower-tri blocks)
__device__ float g_gram[(size_t)BH*SEQ*SEQ];   // k_i . k_j   (lower-tri blocks)

// tf32 split operands (fp32 bit patterns)
__device__ float g_xh [NX],  g_xl [NX];
__device__ float g_Wah[NWA], g_Wal[NWA];
__device__ float g_Wph[NWP], g_Wpl[NWP];
__device__ float g_yh [NX],  g_yl [NX];     // written by dpp epilogue

// ---------------- helpers ----------------
__device__ __forceinline__ float tf32_rnd(float x)
{
    unsigned r;
    asm("cvt.rna.tf32.f32 %0, %1;" : "=r"(r) : "f"(x));
    return __uint_as_float(r);
}

__device__ __forceinline__ void mma_tf32(float* c, const float* a, float b0, float b1)
{
    asm volatile("mma.sync.aligned.m16n8k8.row.col.f32.tf32.tf32.f32 "
        "{%0,%1,%2,%3}, {%4,%5,%6,%7}, {%8,%9}, {%0,%1,%2,%3};"
        : "+f"(c[0]), "+f"(c[1]), "+f"(c[2]), "+f"(c[3])
        : "r"(__float_as_uint(a[0])), "r"(__float_as_uint(a[1])),
          "r"(__float_as_uint(a[2])), "r"(__float_as_uint(a[3])),
          "r"(__float_as_uint(b0)),   "r"(__float_as_uint(b1)));
}

__device__ __forceinline__ void cp16(unsigned dst, const float* src)
{
    asm volatile("cp.async.ca.shared.global [%0], [%1], 16;" :: "r"(dst), "l"(src));
}

// monotonic float<->u32 map: preserves total order, NaN maps above +inf
__device__ __forceinline__ unsigned fmap(float v)
{
    unsigned u = __float_as_uint(v);
    return (u & 0x80000000u) ? ~u : (u | 0x80000000u);
}
__device__ __forceinline__ float funmap(unsigned m)
{
    unsigned u = (m & 0x80000000u) ? (m ^ 0x80000000u) : ~m;
    return __uint_as_float(u);
}

// ---------------- fused split kernel: x, W_attn, W_proj -> tf32 hi/lo ------
__global__ __launch_bounds__(256)
void split3_kernel(const float* __restrict__ x, const float* __restrict__ wa,
                   const float* __restrict__ wp)
{
    int i = (blockIdx.x*256 + threadIdx.x) * 4;
    const float* s; float *hi, *lo; int off;
    if (i < NX)              { s = x;  hi = g_xh;  lo = g_xl;  off = i; }
    else if (i < NX+NWA)     { s = wa; hi = g_Wah; lo = g_Wal; off = i - NX; }
    else if (i < NX+NWA+NWP) { s = wp; hi = g_Wph; lo = g_Wpl; off = i - NX - NWA; }
    else return;
    float4 v = *(const float4*)(s + off);
    float4 h, l;
    h.x = tf32_rnd(v.x); l.x = tf32_rnd(v.x - h.x);
    h.y = tf32_rnd(v.y); l.y = tf32_rnd(v.y - h.y);
    h.z = tf32_rnd(v.z); l.z = tf32_rnd(v.z - h.z);
    h.w = tf32_rnd(v.w); l.w = tf32_rnd(v.w - h.w);
    *(float4*)&hi[off] = h;
    *(float4*)&lo[off] = l;
}

// ---------------- qkv scatter ----------------
__device__ __forceinline__ void scatter_qkv(int row, int gc, float v0, float v1)
{
    int sect = gc / CDIM;              // 0=q 1=k 2=v
    int cc = gc - sect*CDIM;
    int h = cc >> 6, dd = cc & 63;
    int bb = row >> 9, t = row & 511;
    size_t off = ((size_t)(bb*NHEAD + h)*SEQ + t)*HS + dd;
    float* dst = (sect == 0) ? g_q : (sect == 1 ? g_k : g_v);
    *(float2*)&dst[off] = make_float2(v0, v1);
}

// ---------------- 3xTF32 GEMM, cp.async 2-stage, K-chunk 16 (proven) ------
#define STGF 9472
#define GEMM_SMEM (2*STGF*4)

__global__ __launch_bounds__(256, 2)
void tf32_gemm(const float* __restrict__ bias, float* __restrict__ Cout,
               int M, int N, int K, int mode)
{
    extern __shared__ __align__(16) float sm[];

    const float *Ah, *Al, *Bh, *Bl;
    if (mode == 0) { Ah = g_xh; Al = g_xl; Bh = g_Wah; Bl = g_Wal; }
    else           { Ah = g_yh; Al = g_yl; Bh = g_Wph; Bl = g_Wpl; }

    const int tid = threadIdx.x, lane = tid & 31, wid = tid >> 5;
    const int bm = blockIdx.y, bn = blockIdx.x;
    const int wm = wid & 3, wn = wid >> 2;
    const int g = lane >> 2, t = lane & 3;

    const unsigned smbase = (unsigned)__cvta_generic_to_shared(sm);

    float acc[2][8][4];
#pragma unroll
    for (int a = 0; a < 2; a++)
#pragma unroll
        for (int b = 0; b < 8; b++)
#pragma unroll
            for (int c = 0; c < 4; c++) acc[a][b][c] = 0.f;

    const int NC = K >> 4;

    auto issue = [&](int s, int k0) {
        unsigned base = smbase + (unsigned)(s*STGF)*4u;
#pragma unroll
        for (int j = 0; j < 4; j++) {
            int id = tid + 256*j;
            int sp = id >> 9, rem = id & 511, row = rem >> 2, q = (rem & 3)*4;
            const float* src = (sp ? Al : Ah) + (size_t)(bm*128 + row)*K + k0 + q;
            cp16(base + (unsigned)(sp*2560 + row*20 + q)*4u, src);
        }
#pragma unroll
        for (int j = 0; j < 4; j++) {
            int id = tid + 256*j;
            int sp = id >> 9, rem = id & 511, kr = rem >> 5, nq = (rem & 31)*4;
            const float* src = (sp ? Bl : Bh) + (size_t)(k0 + kr)*N + bn*128 + nq;
            cp16(base + (unsigned)(5120 + sp*2176 + kr*136 + nq)*4u, src);
        }
        asm volatile("cp.async.commit_group;");
    };

    issue(0, 0);

    for (int c = 0; c < NC; c++) {
        if (c + 1 < NC) {
            issue((c+1) & 1, (c+1)*16);
            asm volatile("cp.async.wait_group 1;");
        } else {
            asm volatile("cp.async.wait_group 0;");
        }
        __syncthreads();

        const float* S = sm + (c & 1)*STGF;

#pragma unroll
        for (int ks = 0; ks < 16; ks += 8) {
            float ah[2][4], al[2][4];
#pragma unroll
            for (int mt = 0; mt < 2; mt++) {
                int m0 = (wm*32 + mt*16 + g)*20 + ks + t;
                ah[mt][0] = S[m0];          ah[mt][1] = S[m0 + 160];
                ah[mt][2] = S[m0 + 4];      ah[mt][3] = S[m0 + 164];
                al[mt][0] = S[2560 + m0];   al[mt][1] = S[2560 + m0 + 160];
                al[mt][2] = S[2560 + m0+4]; al[mt][3] = S[2560 + m0 + 164];
            }
            int nb0 = wn*64 + g;
            float bh0 = S[5120 + (ks+t)*136 + nb0];
            float bh1 = S[5120 + (ks+t+4)*136 + nb0];
            float bl0 = S[7296 + (ks+t)*136 + nb0];
            float bl1 = S[7296 + (ks+t+4)*136 + nb0];
#pragma unroll
            for (int nt = 0; nt < 8; nt++) {
                float cbh0 = bh0, cbh1 = bh1, cbl0 = bl0, cbl1 = bl1;
                if (nt < 7) {
                    int nb = wn*64 + (nt+1)*8 + g;
                    bh0 = S[5120 + (ks+t)*136 + nb];
                    bh1 = S[5120 + (ks+t+4)*136 + nb];
                    bl0 = S[7296 + (ks+t)*136 + nb];
                    bl1 = S[7296 + (ks+t+4)*136 + nb];
                }
#pragma unroll
                for (int mt = 0; mt < 2; mt++) {
                    mma_tf32(acc[mt][nt], ah[mt], cbh0, cbh1);
                    mma_tf32(acc[mt][nt], ah[mt], cbl0, cbl1);
                    mma_tf32(acc[mt][nt], al[mt], cbh0, cbh1);
                }
            }
        }
        __syncthreads();
    }

#pragma unroll
    for (int mt = 0; mt < 2; mt++) {
        int r0 = bm*128 + wm*32 + mt*16 + g;
#pragma unroll
        for (int nt = 0; nt < 8; nt++) {
            int gc = bn*128 + wn*64 + nt*8 + t*2;
            float b0 = bias[gc], b1 = bias[gc+1];
            float v00 = acc[mt][nt][0] + b0, v01 = acc[mt][nt][1] + b1;
            float v10 = acc[mt][nt][2] + b0, v11 = acc[mt][nt][3] + b1;
            if (mode == 1) {
                *(float2*)&Cout[(size_t)r0*N + gc]     = make_float2(v00, v01);
                *(float2*)&Cout[(size_t)(r0+8)*N + gc] = make_float2(v10, v11);
            } else {
                scatter_qkv(r0,     gc, v00, v01);
                scatter_qkv(r0 + 8, gc, v10, v11);
            }
        }
    }
}

// ---------------- sim/gram: Out = A K^T per head, 3xTF32, lower-tri -------
// mode 0: A = q -> g_sim      mode 1: A = k -> g_gram
#define APITCH 20
__global__ __launch_bounds__(256)
void sim_tf32(int mode)
{
    const int bm = blockIdx.y, bn = blockIdx.x;
    if (bn > bm) return;
    const int bh = blockIdx.z;

    __shared__ __align__(16) float Qs[2][128*APITCH];
    __shared__ __align__(16) float Ks[2][128*APITCH];

    const float* __restrict__ qb = (mode ? g_k : g_q) + (size_t)bh*SEQ*HS;
    const float* __restrict__ kb = g_k + (size_t)bh*SEQ*HS;

    const int tid = threadIdx.x, lane = tid & 31, wid = tid >> 5;
    const int wm = wid & 3, wn = wid >> 2;
    const int g = lane >> 2, t = lane & 3;

    float acc[2][8][4];
#pragma unroll
    for (int a = 0; a < 2; a++)
#pragma unroll
        for (int b = 0; b < 8; b++)
#pragma unroll
            for (int c = 0; c < 4; c++) acc[a][b][c] = 0.f;

    for (int d0 = 0; d0 < HS; d0 += 16) {
        if (d0 > 0) __syncthreads();
#pragma unroll
        for (int j = 0; j < 2; j++) {
            int id = tid*2 + j;
            int r = id >> 2, c = (id & 3)*4;
            float4 qv = *(const float4*)&qb[(size_t)(bm*128 + r)*HS + d0 + c];
            float4 kv = *(const float4*)&kb[(size_t)(bn*128 + r)*HS + d0 + c];
            float4 qh, ql, kh, kl;
            qh.x = tf32_rnd(qv.x); ql.x = tf32_rnd(qv.x - qh.x);
            qh.y = tf32_rnd(qv.y); ql.y = tf32_rnd(qv.y - qh.y);
            qh.z = tf32_rnd(qv.z); ql.z = tf32_rnd(qv.z - qh.z);
            qh.w = tf32_rnd(qv.w); ql.w = tf32_rnd(qv.w - qh.w);
            kh.x = tf32_rnd(kv.x); kl.x = tf32_rnd(kv.x - kh.x);
            kh.y = tf32_rnd(kv.y); kl.y = tf32_rnd(kv.y - kh.y);
            kh.z = tf32_rnd(kv.z); kl.z = tf32_rnd(kv.z - kh.z);
            kh.w = tf32_rnd(kv.w); kl.w = tf32_rnd(kv.w - kh.w);
            *(float4*)&Qs[0][r*APITCH + c] = qh;
            *(float4*)&Qs[1][r*APITCH + c] = ql;
            *(float4*)&Ks[0][r*APITCH + c] = kh;
            *(float4*)&Ks[1][r*APITCH + c] = kl;
        }
        __syncthreads();

#pragma unroll
        for (int ks = 0; ks < 16; ks += 8) {
            float ah[2][4], al[2][4];
#pragma unroll
            for (int mt = 0; mt < 2; mt++) {
                int m0 = (wm*32 + mt*16 + g)*APITCH + ks + t;
                int m1 = m0 + 8*APITCH;
                ah[mt][0] = Qs[0][m0];   ah[mt][1] = Qs[0][m1];
                ah[mt][2] = Qs[0][m0+4]; ah[mt][3] = Qs[0][m1+4];
                al[mt][0] = Qs[1][m0];   al[mt][1] = Qs[1][m1];
                al[mt][2] = Qs[1][m0+4]; al[mt][3] = Qs[1][m1+4];
            }
#pragma unroll
            for (int nt = 0; nt < 8; nt++) {
                int n0 = (wn*64 + nt*8 + g)*APITCH + ks + t;
                float bh0 = Ks[0][n0];
                float bh1 = Ks[0][n0+4];
                float bl0 = Ks[1][n0];
                float bl1 = Ks[1][n0+4];
#pragma unroll
                for (int mt = 0; mt < 2; mt++) {
                    mma_tf32(acc[mt][nt], ah[mt], bh0, bh1);
                    mma_tf32(acc[mt][nt], ah[mt], bl0, bl1);
                    mma_tf32(acc[mt][nt], al[mt], bh0, bh1);
                }
            }
        }
    }

    float* S = (mode ? g_gram : g_sim) + (size_t)bh*SEQ*SEQ;
#pragma unroll
    for (int mt = 0; mt < 2; mt++) {
        int r0 = bm*128 + wm*32 + mt*16 + g;
#pragma unroll
        for (int nt = 0; nt < 8; nt++) {
            int gc = bn*128 + wn*64 + nt*8 + t*2;
            *(float2*)&S[(size_t)r0*SEQ + gc]     = make_float2(acc[mt][nt][0], acc[mt][nt][1]);
            *(float2*)&S[(size_t)(r0+8)*SEQ + gc] = make_float2(acc[mt][nt][2], acc[mt][nt][3]);
        }
    }
}

// ---------------- DPP: gram gathered from g_gram (no staging/compute) -----
__global__ __launch_bounds__(32*DW)
void dpp_kernel()
{
    __shared__ float Gm[DW][17][17];

    const unsigned FULL = 0xffffffffu;
    const int lane = threadIdx.x & 31;
    const int wrp  = threadIdx.x >> 5;
    const int i  = blockIdx.x * DW + wrp;
    const int bh = blockIdx.y;
    const int nvalid = i + 1;

    const float* __restrict__ vb = g_v + (size_t)bh*SEQ*HS;
    const float* __restrict__ simRow = g_sim + ((size_t)bh*SEQ + i)*SEQ;
    const float* __restrict__ Gh = g_gram + (size_t)bh*SEQ*SEQ;

    // ---- lane-major sim load: val[c] = sim[lane*16 + c] ----
    float val[16];
    {
        const float4* sr = (const float4*)simRow;
#pragma unroll
        for (int q = 0; q < 4; q++) {
            float4 v4 = sr[lane*4 + q];
            val[q*4+0] = v4.x; val[q*4+1] = v4.y;
            val[q*4+2] = v4.z; val[q*4+3] = v4.w;
        }
    }
    int cnt = nvalid - lane*16;
    cnt = (cnt < 0) ? 0 : (cnt > 16 ? 16 : cnt);
    unsigned dead = (0xFFFFu << cnt) & 0xFFFFu;

    // initial local top-2 (strict > keeps lowest c)
    float bv1 = -INFINITY, bv2 = -INFINITY; int bc1 = 0, bc2 = 0;
#pragma unroll
    for (int c = 0; c < 16; c++) {
        float v = ((dead >> c) & 1u) ? -INFINITY : val[c];
        if (v > bv1)      { bv2 = bv1; bc2 = bc1; bv1 = v; bc1 = c; }
        else if (v > bv2) { bv2 = v; bc2 = c; }
    }
    bool have2 = true;

    // ---- top-16 extraction ----
    float myVal = -INFINITY; int myIdx = i;
    for (int t = 0; t < 16; t++) {
        unsigned m = fmap(bv1);
        unsigned mmax = __reduce_max_sync(FULL, m);
        unsigned ball = __ballot_sync(FULL, m == mmax);
        int wl = __ffs(ball) - 1;
        int wc = __shfl_sync(FULL, bc1, wl);
        if (lane == t) { myVal = funmap(mmax); myIdx = wl*16 + wc; }
        if (lane == wl) {
            dead |= 1u << bc1;
            if (have2) {
                bv1 = bv2; bc1 = bc2; have2 = false;
            } else {
                bv1 = -INFINITY; bc1 = 0; bv2 = -INFINITY; bc2 = 0;
#pragma unroll
                for (int c = 0; c < 16; c++) {
                    float v = ((dead >> c) & 1u) ? -INFINITY : val[c];
                    if (v > bv1)      { bv2 = bv1; bc2 = bc1; bv1 = v; bc1 = c; }
                    else if (v > bv2) { bv2 = v; bc2 = c; }
                }
                have2 = true;
            }
        }
    }
    bool availb = (lane < 16) && (myVal > -INFINITY) && (myIdx != i);
    unsigned avail = __ballot_sync(FULL, availb) & 0xFFFFu;
    int safeIdx = (lane < 16 && myVal > -INFINITY) ? myIdx : i;

    // ---- gather 17x17 gram from g_gram (lower-tri storage) ----
#pragma unroll
    for (int t2 = 0; t2 < 10; t2++) {
        int e = lane + 32*t2;
        int a = e / 17, b = e - a*17;
        int ta = __shfl_sync(FULL, safeIdx, a & 15);
        int tb = __shfl_sync(FULL, safeIdx, b & 15);
        if (e < 289) {
            int t_a = (a >= 16) ? i : ta;
            int t_b = (b >= 16) ? i : tb;
            int row = max(t_a, t_b), col = min(t_a, t_b);
            Gm[wrp][a][b] = Gh[(size_t)row*SEQ + col];
        }
    }
    __syncwarp();

    // ---- greedy loop with incremental Cholesky ----
    const int cl = lane & 15;
    float Gii  = Gm[wrp][16][16];
    float detS = Gii;
    float curS = -logf(Gii + 1e-6f);
    int count = 1;
    float w[8];
    float w0 = Gm[wrp][cl][16] / sqrtf(Gii);
    w[0] = w0;
#pragma unroll
    for (int j = 1; j < 8; j++) w[j] = 0.f;
    float ec = Gm[wrp][cl][cl] - w0*w0;
    int selTok[8];
#pragma unroll
    for (int j = 0; j < 8; j++) selTok[j] = i;

    for (int step = 0; step < 7; step++) {
        bool av = (lane < 16) && ((avail >> lane) & 1u);
        float s = av ? (-logf(detS*ec + 1e-6f) / (float)(count + 1)) : -INFINITY;
        unsigned m = fmap(s);
        unsigned mmax = __reduce_max_sync(FULL, m);
        unsigned ball = __ballot_sync(FULL, m == mmax);
        int bl = __ffs(ball) - 1;
        float bs = funmap(mmax);

        bool anyAvail = (avail != 0u);
        bool accept = anyAvail && ((bs > curS) || (count < 2));
        if (!accept) break;

        float eb = __shfl_sync(FULL, ec, bl);
        float Lb = sqrtf(eb);
        float dot = 0.f;
#pragma unroll
        for (int j = 0; j < 7; j++) {
            float wbj = __shfl_sync(FULL, w[j], bl);
            if (j < count) dot += w[j]*wbj;
        }
        float wn = (Gm[wrp][cl][bl] - dot) / Lb;
#pragma unroll
        for (int j = 1; j < 8; j++) if (j == count) w[j] = wn;
        ec -= wn*wn;
        detS *= eb;
        curS = bs;
        int btok = __shfl_sync(FULL, myIdx, bl);
#pragma unroll
        for (int j = 1; j < 8; j++) if (j == count) selTok[j] = btok;
        count++;
        avail &= ~(1u << bl);
    }

    // ---- y_i = mean of selected v rows; write tf32 hi/lo directly ----
    float a0 = 0.f, a1 = 0.f;
#pragma unroll
    for (int r = 0; r < 8; r++) {
        if (r < count) {
            const float* vr = vb + (size_t)selTok[r]*HS;
            a0 += vr[lane];
            a1 += vr[lane + 32];
        }
    }
    float cnt2 = (float)count;
    float o0 = a0 / cnt2, o1 = a1 / cnt2;
    int bb = bh / NHEAD, h = bh % NHEAD;
    size_t yoff = ((size_t)(bb*SEQ + i))*CDIM + h*HS;
    float h0 = tf32_rnd(o0), l0 = tf32_rnd(o0 - h0);
    float h1 = tf32_rnd(o1), l1 = tf32_rnd(o1 - h1);
    g_yh[yoff + lane]      = h0;  g_yl[yoff + lane]      = l0;
    g_yh[yoff + lane + 32] = h1;  g_yl[yoff + lane + 32] = l1;
}

// ---------------------------------------------------------------------------
extern "C" void kernel_launch(void* const* d_in, const int* in_sizes, int n_in,
                              void* d_out, int out_size)
{
    const float* x      = (const float*)d_in[0];
    const float* W_attn = (const float*)d_in[1];
    const float* b_attn = (const float*)d_in[2];
    const float* W_proj = (const float*)d_in[3];
    const float* b_proj = (const float*)d_in[4];
    float* out = (float*)d_out;

    static int smem_set = 0;
    if (!smem_set) {
        cudaFuncSetAttribute(tf32_gemm,
                             cudaFuncAttributeMaxDynamicSharedMemorySize,
                             GEMM_SMEM);
        smem_set = 1;
    }

    const int ntot = NX + NWA + NWP;
    split3_kernel<<<(ntot/4 + 255)/256, 256>>>(x, W_attn, W_proj);

    {   // QKV: [2048,768] @ [768,2304] -> scatter q/k/v (fp32)
        dim3 grid(3*CDIM/128, (BATCH*SEQ)/128);
        tf32_gemm<<<grid, 256, GEMM_SMEM>>>(b_attn, out, BATCH*SEQ, 3*CDIM, CDIM, 0);
    }
    {   // sim: S = Q K^T ; gram: G = K K^T (lower-tri blocks, per head)
        dim3 grid(4, 4, BH);
        sim_tf32<<<grid, 256>>>(0);
        sim_tf32<<<grid, 256>>>(1);
    }
    {   // DPP attention -> g_yh/g_yl
        dim3 grid(SEQ/DW, BH);
        dpp_kernel<<<grid, 32*DW>>>();
    }
    {   // Proj: [2048,768] @ [768,768] -> out
        dim3 grid(CDIM/128, (BATCH*SEQ)/128);
        tf32_gemm<<<grid, 256, GEMM_SMEM>>>(b_proj, out, BATCH*SEQ, CDIM, CDIM, 1);
    }
}